// round 1
// baseline (speedup 1.0000x reference)
#include <cuda_runtime.h>
#include <math.h>

#define B_ 2
#define S_ 2048
#define D_ 1024
#define H_ 16
#define DK_ 64
#define FF_ 4096
#define NEG_ (-1000000000.0f)

// ---------------- scratch buffers (no allocation allowed) ----------------
__device__ float g_n1[(size_t)B_ * S_ * D_];   // LN1 output
__device__ float g_q [(size_t)B_ * S_ * D_];
__device__ float g_k [(size_t)B_ * S_ * D_];
__device__ float g_v [(size_t)B_ * S_ * D_];
__device__ float g_o [(size_t)B_ * S_ * D_];   // attention output (pre-proj)
__device__ float g_x1[(size_t)B_ * S_ * D_];   // x + attn_proj
__device__ float g_n2[(size_t)B_ * S_ * D_];   // LN2 output
__device__ float g_ff[(size_t)B_ * S_ * FF_];  // gelu(n2@W1+b)

// ---------------- LayerNorm: one block per row of D=1024 ----------------
__global__ __launch_bounds__(256) void ln_kernel(const float* __restrict__ x,
                                                 const float* __restrict__ g,
                                                 const float* __restrict__ b,
                                                 float* __restrict__ out)
{
    const int row = blockIdx.x;
    const float* xr = x + (size_t)row * D_;
    float* outr = out + (size_t)row * D_;
    const int tid = threadIdx.x;

    float4 v = reinterpret_cast<const float4*>(xr)[tid];  // 256 thr * 4 = 1024
    float s = v.x + v.y + v.z + v.w;
    float ss = v.x * v.x + v.y * v.y + v.z * v.z + v.w * v.w;

    // block reduce (sum, sumsq)
    __shared__ float sh_s[8], sh_ss[8];
    for (int off = 16; off; off >>= 1) {
        s  += __shfl_xor_sync(0xffffffffu, s, off);
        ss += __shfl_xor_sync(0xffffffffu, ss, off);
    }
    const int wid = tid >> 5, lane = tid & 31;
    if (lane == 0) { sh_s[wid] = s; sh_ss[wid] = ss; }
    __syncthreads();
    if (wid == 0) {
        s  = (lane < 8) ? sh_s[lane]  : 0.f;
        ss = (lane < 8) ? sh_ss[lane] : 0.f;
        for (int off = 4; off; off >>= 1) {
            s  += __shfl_xor_sync(0xffffffffu, s, off);
            ss += __shfl_xor_sync(0xffffffffu, ss, off);
        }
        if (lane == 0) { sh_s[0] = s; sh_ss[0] = ss; }
    }
    __syncthreads();
    const float mu = sh_s[0] * (1.0f / D_);
    const float var = sh_ss[0] * (1.0f / D_) - mu * mu;
    const float rstd = rsqrtf(var + 1e-5f);

    float4 gv = reinterpret_cast<const float4*>(g)[tid];
    float4 bv = reinterpret_cast<const float4*>(b)[tid];
    float4 o;
    o.x = (v.x - mu) * rstd * gv.x + bv.x;
    o.y = (v.y - mu) * rstd * gv.y + bv.y;
    o.z = (v.z - mu) * rstd * gv.z + bv.z;
    o.w = (v.w - mu) * rstd * gv.w + bv.w;
    reinterpret_cast<float4*>(outr)[tid] = o;
}

// ---------------- SGEMM: C = act(A[MxK] @ W[KxN] + bias) + res ----------------
// BM=BN=128, BK=8, 256 threads, 8x8 micro-tile. All dims multiples of 128/8.
#define BM 128
#define BN 128
#define BK 8
__global__ __launch_bounds__(256) void sgemm_kernel(const float* __restrict__ A,
                                                    const float* __restrict__ W,
                                                    const float* __restrict__ bias,
                                                    const float* __restrict__ res,
                                                    float* __restrict__ C,
                                                    int M, int N, int K, int act)
{
    __shared__ float As[BK][BM];
    __shared__ float Bs[BK][BN];

    const int tid = threadIdx.x;
    const int row0 = blockIdx.y * BM;
    const int col0 = blockIdx.x * BN;
    const int tx = tid & 15;   // 16 thread-cols
    const int ty = tid >> 4;   // 16 thread-rows

    // A tile loader: 128x8 floats, each thread one float4 along K
    const int a_r = tid >> 1;
    const int a_c = (tid & 1) << 2;
    // B tile loader: 8x128 floats, each thread one float4 along N
    const int b_r = tid >> 5;
    const int b_c = (tid & 31) << 2;

    float acc[8][8];
#pragma unroll
    for (int i = 0; i < 8; i++)
#pragma unroll
        for (int j = 0; j < 8; j++) acc[i][j] = 0.f;

    for (int k0 = 0; k0 < K; k0 += BK) {
        float4 av = *reinterpret_cast<const float4*>(&A[(size_t)(row0 + a_r) * K + k0 + a_c]);
        As[a_c + 0][a_r] = av.x;
        As[a_c + 1][a_r] = av.y;
        As[a_c + 2][a_r] = av.z;
        As[a_c + 3][a_r] = av.w;
        float4 bv4 = *reinterpret_cast<const float4*>(&W[(size_t)(k0 + b_r) * N + col0 + b_c]);
        *reinterpret_cast<float4*>(&Bs[b_r][b_c]) = bv4;
        __syncthreads();

#pragma unroll
        for (int kk = 0; kk < BK; kk++) {
            float a[8], b[8];
#pragma unroll
            for (int i = 0; i < 8; i++) a[i] = As[kk][ty * 8 + i];
#pragma unroll
            for (int j = 0; j < 8; j++) b[j] = Bs[kk][tx * 8 + j];
#pragma unroll
            for (int i = 0; i < 8; i++)
#pragma unroll
                for (int j = 0; j < 8; j++) acc[i][j] = fmaf(a[i], b[j], acc[i][j]);
        }
        __syncthreads();
    }

    // epilogue
#pragma unroll
    for (int i = 0; i < 8; i++) {
        const int r = row0 + ty * 8 + i;
#pragma unroll
        for (int j = 0; j < 8; j += 4) {
            const int c = col0 + tx * 8 + j;
            float4 o;
            o.x = acc[i][j + 0] + bias[c + 0];
            o.y = acc[i][j + 1] + bias[c + 1];
            o.z = acc[i][j + 2] + bias[c + 2];
            o.w = acc[i][j + 3] + bias[c + 3];
            if (act == 1) {  // exact GELU
                o.x = 0.5f * o.x * (1.0f + erff(o.x * 0.70710678118654752f));
                o.y = 0.5f * o.y * (1.0f + erff(o.y * 0.70710678118654752f));
                o.z = 0.5f * o.z * (1.0f + erff(o.z * 0.70710678118654752f));
                o.w = 0.5f * o.w * (1.0f + erff(o.w * 0.70710678118654752f));
            }
            if (res) {
                float4 rv = *reinterpret_cast<const float4*>(&res[(size_t)r * N + c]);
                o.x += rv.x; o.y += rv.y; o.z += rv.z; o.w += rv.w;
            }
            *reinterpret_cast<float4*>(&C[(size_t)r * N + c]) = o;
        }
    }
}

// ---------------- Sparse attention: one warp per (b, h, query) ----------------
// Allowed keys: j in [max(0,i-128), i]  plus  j = i-256, i-384, ... (j >= 0)
__global__ __launch_bounds__(128) void attn_kernel(const float* __restrict__ Q,
                                                   const float* __restrict__ K,
                                                   const float* __restrict__ V,
                                                   const int* __restrict__ mask,
                                                   float* __restrict__ O)
{
    const int warp = threadIdx.x >> 5;
    const int lane = threadIdx.x & 31;
    const int i = blockIdx.x * 4 + warp;  // query index
    const int h = blockIdx.y;
    const int b = blockIdx.z;

    const size_t head_off = (size_t)h * DK_;
    const float* qrow = Q + ((size_t)(b * S_ + i)) * D_ + head_off;
    const float q0 = qrow[lane];
    const float q1 = qrow[lane + 32];

    const float* Kb = K + ((size_t)b * S_) * D_ + head_off;
    const float* Vb = V + ((size_t)b * S_) * D_ + head_off;
    const int* mrow = mask + (size_t)i * S_;

    float m = -INFINITY, l = 0.f, acc0 = 0.f, acc1 = 0.f;

#define PROCESS_KEY(j)                                                        \
    {                                                                         \
        const float* krow = Kb + (size_t)(j) * D_;                            \
        float s = q0 * krow[lane] + q1 * krow[lane + 32];                     \
        for (int off = 16; off; off >>= 1)                                    \
            s += __shfl_xor_sync(0xffffffffu, s, off);                        \
        s *= 0.125f; /* 1/sqrt(64) */                                         \
        if (mrow[j] == 0) s = NEG_;                                           \
        float nm = fmaxf(m, s);                                               \
        float sc = __expf(m - nm);                                            \
        float p = __expf(s - nm);                                             \
        l = l * sc + p;                                                       \
        const float* vrow = Vb + (size_t)(j) * D_;                            \
        acc0 = acc0 * sc + p * vrow[lane];                                    \
        acc1 = acc1 * sc + p * vrow[lane + 32];                               \
        m = nm;                                                               \
    }

    // strided-only keys (distance >= 256, multiple of 128)
    for (int j = i - 256; j >= 0; j -= 128) PROCESS_KEY(j);
    // local window keys
    int jlo = i - 128;
    if (jlo < 0) jlo = 0;
    for (int j = jlo; j <= i; j++) PROCESS_KEY(j);
#undef PROCESS_KEY

    const float inv = 1.0f / l;
    float* orow = O + ((size_t)(b * S_ + i)) * D_ + head_off;
    orow[lane] = acc0 * inv;
    orow[lane + 32] = acc1 * inv;
}

// ---------------- host launcher ----------------
extern "C" void kernel_launch(void* const* d_in, const int* in_sizes, int n_in,
                              void* d_out, int out_size)
{
    (void)in_sizes; (void)n_in; (void)out_size;
    const float* x    = (const float*)d_in[0];
    const int*   mask = (const int*)  d_in[1];
    const float* Wq = (const float*)d_in[2];  const float* bq = (const float*)d_in[3];
    const float* Wk = (const float*)d_in[4];  const float* bk = (const float*)d_in[5];
    const float* Wv = (const float*)d_in[6];  const float* bv = (const float*)d_in[7];
    const float* Wo = (const float*)d_in[8];  const float* bo = (const float*)d_in[9];
    const float* W1 = (const float*)d_in[10]; const float* bf1 = (const float*)d_in[11];
    const float* W2 = (const float*)d_in[12]; const float* bf2 = (const float*)d_in[13];
    const float* g1 = (const float*)d_in[14]; const float* bl1 = (const float*)d_in[15];
    const float* g2 = (const float*)d_in[16]; const float* bl2 = (const float*)d_in[17];
    float* out = (float*)d_out;

    float *n1, *q, *k, *v, *o, *x1, *n2, *ff;
    cudaGetSymbolAddress((void**)&n1, g_n1);
    cudaGetSymbolAddress((void**)&q,  g_q);
    cudaGetSymbolAddress((void**)&k,  g_k);
    cudaGetSymbolAddress((void**)&v,  g_v);
    cudaGetSymbolAddress((void**)&o,  g_o);
    cudaGetSymbolAddress((void**)&x1, g_x1);
    cudaGetSymbolAddress((void**)&n2, g_n2);
    cudaGetSymbolAddress((void**)&ff, g_ff);

    const int M = B_ * S_;  // 4096

    // 1) LN1
    ln_kernel<<<M, 256>>>(x, g1, bl1, n1);

    // 2) Q, K, V projections
    {
        dim3 grid(D_ / BN, M / BM);
        sgemm_kernel<<<grid, 256>>>(n1, Wq, bq, nullptr, q, M, D_, D_, 0);
        sgemm_kernel<<<grid, 256>>>(n1, Wk, bk, nullptr, k, M, D_, D_, 0);
        sgemm_kernel<<<grid, 256>>>(n1, Wv, bv, nullptr, v, M, D_, D_, 0);
    }

    // 3) sparse attention -> o in [B,S,D] layout
    {
        dim3 grid(S_ / 4, H_, B_);
        attn_kernel<<<grid, 128>>>(q, k, v, mask, o);
    }

    // 4) output projection + residual: x1 = x + o @ Wo + bo
    {
        dim3 grid(D_ / BN, M / BM);
        sgemm_kernel<<<grid, 256>>>(o, Wo, bo, x, x1, M, D_, D_, 0);
    }

    // 5) LN2
    ln_kernel<<<M, 256>>>(x1, g2, bl2, n2);

    // 6) FFN up + exact GELU: ff = gelu(n2 @ W1 + bf1)
    {
        dim3 grid(FF_ / BN, M / BM);
        sgemm_kernel<<<grid, 256>>>(n2, W1, bf1, nullptr, ff, M, FF_, D_, 1);
    }

    // 7) FFN down + residual: out = x1 + ff @ W2 + bf2
    {
        dim3 grid(D_ / BN, M / BM);
        sgemm_kernel<<<grid, 256>>>(ff, W2, bf2, x1, out, M, D_, FF_, 0);
    }
}

// round 3
// speedup vs baseline: 2.1778x; 2.1778x over previous
#include <cuda_runtime.h>
#include <math.h>
#include <stdint.h>

#define B_ 2
#define S_ 2048
#define D_ 1024
#define H_ 16
#define DK_ 64
#define FF_ 4096
#define NEG_ (-1000000000.0f)

// ---------------- scratch buffers ----------------
__device__ float g_n1[(size_t)B_ * S_ * D_];
__device__ float g_q [(size_t)B_ * S_ * D_];
__device__ float g_k [(size_t)B_ * S_ * D_];
__device__ float g_v [(size_t)B_ * S_ * D_];
__device__ float g_o [(size_t)B_ * S_ * D_];
__device__ float g_x1[(size_t)B_ * S_ * D_];
__device__ float g_n2[(size_t)B_ * S_ * D_];
__device__ float g_ff[(size_t)B_ * S_ * FF_];

__device__ __forceinline__ uint32_t f2tf32(float f) {
    uint32_t r; asm("cvt.rna.tf32.f32 %0, %1;" : "=r"(r) : "f"(f)); return r;
}

__device__ __forceinline__ void mma_tf32(float c[4], const uint32_t a[4], const uint32_t b[2]) {
    asm volatile(
        "mma.sync.aligned.m16n8k8.row.col.f32.tf32.tf32.f32 "
        "{%0,%1,%2,%3}, {%4,%5,%6,%7}, {%8,%9}, {%0,%1,%2,%3};"
        : "+f"(c[0]), "+f"(c[1]), "+f"(c[2]), "+f"(c[3])
        : "r"(a[0]), "r"(a[1]), "r"(a[2]), "r"(a[3]), "r"(b[0]), "r"(b[1]));
}

// ---------------- tf32 tensor-core GEMM ----------------
// C[M,N] = act(A[M,K] @ W[K,N] + bias) (+ res)
// CTA tile 128x128, BK=16, 8 warps of 64x32, m16n8k8 tf32 MMA.
#define BM 128
#define BN 128
#define BK 16
#define SPAD 8
#define SSTR (BM + SPAD)   // 136 words: k-row stride (conflict-free frag loads)

__global__ __launch_bounds__(256) void mmagemm_kernel(const float* __restrict__ A,
                                                      const float* __restrict__ W,
                                                      const float* __restrict__ bias,
                                                      const float* __restrict__ res,
                                                      float* __restrict__ C,
                                                      int M, int N, int K, int act)
{
    __shared__ uint32_t As[2][BK][SSTR];   // As[k][m] (tf32)
    __shared__ uint32_t Bs[2][BK][SSTR];   // Bs[k][n] (tf32)

    const int tid = threadIdx.x;
    const int wid = tid >> 5, lane = tid & 31;
    const int row0 = blockIdx.y * BM;
    const int col0 = blockIdx.x * BN;

    // warp tile: 64x32. warp m = wid>>2 (0..1), warp n = wid&3 (0..3)
    const int m0w = (wid >> 2) * 64;
    const int n0w = (wid & 3) * 32;
    const int lg = lane >> 2;   // group id 0..7
    const int lt = lane & 3;    // thread-in-group 0..3

    // A loader: 128 rows x 16 cols, float4 along K; thread -> 2 rows
    const int ar = tid >> 2;          // 0..63
    const int ac = (tid & 3) << 2;    // 0,4,8,12
    // B loader: 16 rows x 128 cols, float4 along N; thread -> 2 rows
    const int br = tid >> 5;          // 0..7
    const int bc = (tid & 31) << 2;   // 0..124

    float acc[4][4][4];
#pragma unroll
    for (int mi = 0; mi < 4; mi++)
#pragma unroll
        for (int ni = 0; ni < 4; ni++)
#pragma unroll
            for (int r = 0; r < 4; r++) acc[mi][ni][r] = 0.f;

    const int NC = K / BK;

    // prologue: tile 0 -> buffer 0
    {
        float4 av0 = *reinterpret_cast<const float4*>(A + (size_t)(row0 + ar) * K + ac);
        float4 av1 = *reinterpret_cast<const float4*>(A + (size_t)(row0 + 64 + ar) * K + ac);
        As[0][ac + 0][ar] = f2tf32(av0.x); As[0][ac + 1][ar] = f2tf32(av0.y);
        As[0][ac + 2][ar] = f2tf32(av0.z); As[0][ac + 3][ar] = f2tf32(av0.w);
        As[0][ac + 0][ar + 64] = f2tf32(av1.x); As[0][ac + 1][ar + 64] = f2tf32(av1.y);
        As[0][ac + 2][ar + 64] = f2tf32(av1.z); As[0][ac + 3][ar + 64] = f2tf32(av1.w);
        float4 bv0 = *reinterpret_cast<const float4*>(W + (size_t)br * N + col0 + bc);
        float4 bv1 = *reinterpret_cast<const float4*>(W + (size_t)(br + 8) * N + col0 + bc);
        uint4 t0 = {f2tf32(bv0.x), f2tf32(bv0.y), f2tf32(bv0.z), f2tf32(bv0.w)};
        uint4 t1 = {f2tf32(bv1.x), f2tf32(bv1.y), f2tf32(bv1.z), f2tf32(bv1.w)};
        *reinterpret_cast<uint4*>(&Bs[0][br][bc]) = t0;
        *reinterpret_cast<uint4*>(&Bs[0][br + 8][bc]) = t1;
    }
    __syncthreads();

    for (int c = 0; c < NC; c++) {
        const int buf = c & 1;
        float4 av0, av1, bv0, bv1;
        if (c + 1 < NC) {
            const int k0 = (c + 1) * BK;
            av0 = *reinterpret_cast<const float4*>(A + (size_t)(row0 + ar) * K + k0 + ac);
            av1 = *reinterpret_cast<const float4*>(A + (size_t)(row0 + 64 + ar) * K + k0 + ac);
            bv0 = *reinterpret_cast<const float4*>(W + (size_t)(k0 + br) * N + col0 + bc);
            bv1 = *reinterpret_cast<const float4*>(W + (size_t)(k0 + 8 + br) * N + col0 + bc);
        }

#pragma unroll
        for (int ks = 0; ks < 2; ks++) {
            const int kk = ks * 8;
            uint32_t afr[4][4], bfr[4][2];
#pragma unroll
            for (int mi = 0; mi < 4; mi++) {
                const int m = m0w + mi * 16 + lg;
                afr[mi][0] = As[buf][kk + lt][m];
                afr[mi][1] = As[buf][kk + lt][m + 8];
                afr[mi][2] = As[buf][kk + lt + 4][m];
                afr[mi][3] = As[buf][kk + lt + 4][m + 8];
            }
#pragma unroll
            for (int ni = 0; ni < 4; ni++) {
                const int n = n0w + ni * 8 + lg;
                bfr[ni][0] = Bs[buf][kk + lt][n];
                bfr[ni][1] = Bs[buf][kk + lt + 4][n];
            }
#pragma unroll
            for (int mi = 0; mi < 4; mi++)
#pragma unroll
                for (int ni = 0; ni < 4; ni++)
                    mma_tf32(acc[mi][ni], afr[mi], bfr[ni]);
        }

        if (c + 1 < NC) {
            const int nb = buf ^ 1;
            As[nb][ac + 0][ar] = f2tf32(av0.x); As[nb][ac + 1][ar] = f2tf32(av0.y);
            As[nb][ac + 2][ar] = f2tf32(av0.z); As[nb][ac + 3][ar] = f2tf32(av0.w);
            As[nb][ac + 0][ar + 64] = f2tf32(av1.x); As[nb][ac + 1][ar + 64] = f2tf32(av1.y);
            As[nb][ac + 2][ar + 64] = f2tf32(av1.z); As[nb][ac + 3][ar + 64] = f2tf32(av1.w);
            uint4 t0 = {f2tf32(bv0.x), f2tf32(bv0.y), f2tf32(bv0.z), f2tf32(bv0.w)};
            uint4 t1 = {f2tf32(bv1.x), f2tf32(bv1.y), f2tf32(bv1.z), f2tf32(bv1.w)};
            *reinterpret_cast<uint4*>(&Bs[nb][br][bc]) = t0;
            *reinterpret_cast<uint4*>(&Bs[nb][br + 8][bc]) = t1;
            __syncthreads();
        }
    }

    // epilogue
#pragma unroll
    for (int mi = 0; mi < 4; mi++) {
#pragma unroll
        for (int half = 0; half < 2; half++) {
            const int r = row0 + m0w + mi * 16 + lg + half * 8;
#pragma unroll
            for (int ni = 0; ni < 4; ni++) {
                const int cc = col0 + n0w + ni * 8 + lt * 2;
                float2 o;
                o.x = acc[mi][ni][half * 2 + 0] + bias[cc];
                o.y = acc[mi][ni][half * 2 + 1] + bias[cc + 1];
                if (act == 1) {
                    o.x = 0.5f * o.x * (1.0f + erff(o.x * 0.70710678118654752f));
                    o.y = 0.5f * o.y * (1.0f + erff(o.y * 0.70710678118654752f));
                }
                if (res) {
                    const float2 rv = *reinterpret_cast<const float2*>(res + (size_t)r * N + cc);
                    o.x += rv.x; o.y += rv.y;
                }
                *reinterpret_cast<float2*>(C + (size_t)r * N + cc) = o;
            }
        }
    }
}

// ---------------- LayerNorm ----------------
__global__ __launch_bounds__(256) void ln_kernel(const float* __restrict__ x,
                                                 const float* __restrict__ g,
                                                 const float* __restrict__ b,
                                                 float* __restrict__ out)
{
    const int row = blockIdx.x;
    const float* xr = x + (size_t)row * D_;
    float* outr = out + (size_t)row * D_;
    const int tid = threadIdx.x;

    float4 v = reinterpret_cast<const float4*>(xr)[tid];
    float s = v.x + v.y + v.z + v.w;
    float ss = v.x * v.x + v.y * v.y + v.z * v.z + v.w * v.w;

    __shared__ float sh_s[8], sh_ss[8];
    for (int off = 16; off; off >>= 1) {
        s  += __shfl_xor_sync(0xffffffffu, s, off);
        ss += __shfl_xor_sync(0xffffffffu, ss, off);
    }
    const int wid = tid >> 5, lane = tid & 31;
    if (lane == 0) { sh_s[wid] = s; sh_ss[wid] = ss; }
    __syncthreads();
    if (wid == 0) {
        s  = (lane < 8) ? sh_s[lane]  : 0.f;
        ss = (lane < 8) ? sh_ss[lane] : 0.f;
        for (int off = 4; off; off >>= 1) {
            s  += __shfl_xor_sync(0xffffffffu, s, off);
            ss += __shfl_xor_sync(0xffffffffu, ss, off);
        }
        if (lane == 0) { sh_s[0] = s; sh_ss[0] = ss; }
    }
    __syncthreads();
    const float mu = sh_s[0] * (1.0f / D_);
    const float var = sh_ss[0] * (1.0f / D_) - mu * mu;
    const float rstd = rsqrtf(var + 1e-5f);

    float4 gv = reinterpret_cast<const float4*>(g)[tid];
    float4 bv = reinterpret_cast<const float4*>(b)[tid];
    float4 o;
    o.x = (v.x - mu) * rstd * gv.x + bv.x;
    o.y = (v.y - mu) * rstd * gv.y + bv.y;
    o.z = (v.z - mu) * rstd * gv.z + bv.z;
    o.w = (v.w - mu) * rstd * gv.w + bv.w;
    reinterpret_cast<float4*>(outr)[tid] = o;
}

// ---------------- sparse attention: one warp per (b, h, query) ----------------
__global__ __launch_bounds__(128) void attn_kernel(const float* __restrict__ Q,
                                                   const float* __restrict__ K,
                                                   const float* __restrict__ V,
                                                   const int* __restrict__ mask,
                                                   float* __restrict__ O)
{
    const int warp = threadIdx.x >> 5;
    const int lane = threadIdx.x & 31;
    const int i = blockIdx.x * 4 + warp;
    const int h = blockIdx.y;
    const int b = blockIdx.z;

    const size_t head_off = (size_t)h * DK_;
    const float* qrow = Q + ((size_t)(b * S_ + i)) * D_ + head_off;
    const float q0 = qrow[lane];
    const float q1 = qrow[lane + 32];

    const float* Kb = K + ((size_t)b * S_) * D_ + head_off;
    const float* Vb = V + ((size_t)b * S_) * D_ + head_off;
    const int* mrow = mask + (size_t)i * S_;

    float m = -INFINITY, l = 0.f, acc0 = 0.f, acc1 = 0.f;

#define PROCESS_KEY(j)                                                        \
    {                                                                         \
        const float* krow = Kb + (size_t)(j) * D_;                            \
        float s = q0 * krow[lane] + q1 * krow[lane + 32];                     \
        for (int off = 16; off; off >>= 1)                                    \
            s += __shfl_xor_sync(0xffffffffu, s, off);                        \
        s *= 0.125f;                                                          \
        if (mrow[j] == 0) s = NEG_;                                           \
        float nm = fmaxf(m, s);                                               \
        float sc = __expf(m - nm);                                            \
        float p = __expf(s - nm);                                             \
        l = l * sc + p;                                                       \
        const float* vrow = Vb + (size_t)(j) * D_;                            \
        acc0 = acc0 * sc + p * vrow[lane];                                    \
        acc1 = acc1 * sc + p * vrow[lane + 32];                               \
        m = nm;                                                               \
    }

    for (int j = i - 256; j >= 0; j -= 128) PROCESS_KEY(j);
    int jlo = i - 128;
    if (jlo < 0) jlo = 0;
    for (int j = jlo; j <= i; j++) PROCESS_KEY(j);
#undef PROCESS_KEY

    const float inv = 1.0f / l;
    float* orow = O + ((size_t)(b * S_ + i)) * D_ + head_off;
    orow[lane] = acc0 * inv;
    orow[lane + 32] = acc1 * inv;
}

// ---------------- host launcher ----------------
extern "C" void kernel_launch(void* const* d_in, const int* in_sizes, int n_in,
                              void* d_out, int out_size)
{
    (void)in_sizes; (void)n_in; (void)out_size;
    const float* x    = (const float*)d_in[0];
    const int*   mask = (const int*)  d_in[1];
    const float* Wq = (const float*)d_in[2];  const float* bq = (const float*)d_in[3];
    const float* Wk = (const float*)d_in[4];  const float* bk = (const float*)d_in[5];
    const float* Wv = (const float*)d_in[6];  const float* bv = (const float*)d_in[7];
    const float* Wo = (const float*)d_in[8];  const float* bo = (const float*)d_in[9];
    const float* W1 = (const float*)d_in[10]; const float* bf1 = (const float*)d_in[11];
    const float* W2 = (const float*)d_in[12]; const float* bf2 = (const float*)d_in[13];
    const float* g1 = (const float*)d_in[14]; const float* bl1 = (const float*)d_in[15];
    const float* g2 = (const float*)d_in[16]; const float* bl2 = (const float*)d_in[17];
    float* out = (float*)d_out;

    float *n1, *q, *k, *v, *o, *x1, *n2, *ff;
    cudaGetSymbolAddress((void**)&n1, g_n1);
    cudaGetSymbolAddress((void**)&q,  g_q);
    cudaGetSymbolAddress((void**)&k,  g_k);
    cudaGetSymbolAddress((void**)&v,  g_v);
    cudaGetSymbolAddress((void**)&o,  g_o);
    cudaGetSymbolAddress((void**)&x1, g_x1);
    cudaGetSymbolAddress((void**)&n2, g_n2);
    cudaGetSymbolAddress((void**)&ff, g_ff);

    const int M = B_ * S_;  // 4096

    // 1) LN1
    ln_kernel<<<M, 256>>>(x, g1, bl1, n1);

    // 2) Q, K, V projections (tf32 mma)
    {
        dim3 grid(D_ / BN, M / BM);
        mmagemm_kernel<<<grid, 256>>>(n1, Wq, bq, nullptr, q, M, D_, D_, 0);
        mmagemm_kernel<<<grid, 256>>>(n1, Wk, bk, nullptr, k, M, D_, D_, 0);
        mmagemm_kernel<<<grid, 256>>>(n1, Wv, bv, nullptr, v, M, D_, D_, 0);
    }

    // 3) sparse attention
    {
        dim3 grid(S_ / 4, H_, B_);
        attn_kernel<<<grid, 128>>>(q, k, v, mask, o);
    }

    // 4) output projection + residual
    {
        dim3 grid(D_ / BN, M / BM);
        mmagemm_kernel<<<grid, 256>>>(o, Wo, bo, x, x1, M, D_, D_, 0);
    }

    // 5) LN2
    ln_kernel<<<M, 256>>>(x1, g2, bl2, n2);

    // 6) FFN up + GELU
    {
        dim3 grid(FF_ / BN, M / BM);
        mmagemm_kernel<<<grid, 256>>>(n2, W1, bf1, nullptr, ff, M, FF_, D_, 1);
    }

    // 7) FFN down + residual
    {
        dim3 grid(D_ / BN, M / BM);
        mmagemm_kernel<<<grid, 256>>>(ff, W2, bf2, x1, out, M, D_, FF_, 0);
    }
}

// round 4
// speedup vs baseline: 2.3560x; 1.0818x over previous
#include <cuda_runtime.h>
#include <math.h>
#include <stdint.h>

#define B_ 2
#define S_ 2048
#define D_ 1024
#define H_ 16
#define DK_ 64
#define FF_ 4096
#define NEG_ (-1000000000.0f)

// ---------------- scratch buffers ----------------
__device__ float g_n1[(size_t)B_ * S_ * D_];
__device__ float g_q [(size_t)B_ * S_ * D_];
__device__ float g_k [(size_t)B_ * S_ * D_];
__device__ float g_v [(size_t)B_ * S_ * D_];
__device__ float g_o [(size_t)B_ * S_ * D_];
__device__ float g_x1[(size_t)B_ * S_ * D_];
__device__ float g_n2[(size_t)B_ * S_ * D_];
__device__ float g_ff[(size_t)B_ * S_ * FF_];

__device__ __forceinline__ uint32_t f2tf32(float f) {
    uint32_t r; asm("cvt.rna.tf32.f32 %0, %1;" : "=r"(r) : "f"(f)); return r;
}

__device__ __forceinline__ void mma_tf32(float c[4], const uint32_t a[4], const uint32_t b[2]) {
    asm volatile(
        "mma.sync.aligned.m16n8k8.row.col.f32.tf32.tf32.f32 "
        "{%0,%1,%2,%3}, {%4,%5,%6,%7}, {%8,%9}, {%0,%1,%2,%3};"
        : "+f"(c[0]), "+f"(c[1]), "+f"(c[2]), "+f"(c[3])
        : "r"(a[0]), "r"(a[1]), "r"(a[2]), "r"(a[3]), "r"(b[0]), "r"(b[1]));
}

// ================= tf32 tensor-core GEMM, fragment-packed smem =================
// C[M,N] = act(A[M,K] @ W[K,N] + bias) (+ res)
// CTA tile 128x128, BK=16 (2 k8-blocks), 8 warps of 64x32.
//
// A smem layout (per buffer, 8192B): tile(kb 0..1, g16 0..7) of 512B.
//   slot s = (lg*4 + lt) ^ ((lg>>1)&3), 16B each (lg=m&7, lt=k&3).
//   slot words: [(m,k), (m+8,k), (m,k+4), (m+8,k+4)]  == mma A-fragment order.
// B smem layout (per buffer, 8192B): tile(kb 0..1, g8 0..15) of 256B.
//   slot s = ((n&7)*4 + lt) ^ (g8&3), 8B each; words: [(k,n), (k+4,n)] == B-frag.
#define BM 128
#define BN 128
#define BK 16

__global__ __launch_bounds__(256) void mmagemm_kernel(const float* __restrict__ A,
                                                      const float* __restrict__ W,
                                                      const float* __restrict__ bias,
                                                      const float* __restrict__ res,
                                                      float* __restrict__ C,
                                                      int M, int N, int K, int act)
{
    __shared__ alignas(128) char Asm[2 * 8192];
    __shared__ alignas(128) char Bsm[2 * 8192];

    const int tid = threadIdx.x;
    const int wid = tid >> 5, lane = tid & 31;
    const int row0 = blockIdx.y * BM;
    const int col0 = blockIdx.x * BN;

    const int m0w = (wid >> 2) * 64;      // warp m origin (0 or 64)
    const int n0w = (wid & 3) * 32;       // warp n origin
    const int g16b = m0w >> 4;            // 0 or 4
    const int bg8 = n0w >> 3;             // 0,4,8,12

    // ---- A loader indices: thread handles rows (ar, ar+64), cols ac..ac+3
    const int ar = tid >> 2;
    const int ac = (tid & 3) << 2;
    const int lga = ar & 7;
    const int swa = (lga >> 1) & 3;
    const int abase = ((ac >> 3) * 8 + (ar >> 4)) * 512 +
                      ((((ac >> 2) & 1) * 2) + ((ar >> 3) & 1)) * 4;
    int aoff[4];
#pragma unroll
    for (int j = 0; j < 4; j++) aoff[j] = abase + (((lga * 4 + j) ^ swa) << 4);

    // ---- B loader indices: thread handles n in {nn, nn+64}, k rows kq+{0,4,8,12}
    const int kq = tid >> 6;              // 0..3
    const int nn = tid & 63;
    int boff[2][2];                        // [t (n half)][kb]
#pragma unroll
    for (int t = 0; t < 2; t++) {
        const int nv = nn + t * 64;
        const int g8 = nv >> 3;
        const int slot = (((nv & 7) * 4 + kq) ^ (g8 & 3));
#pragma unroll
        for (int kb = 0; kb < 2; kb++)
            boff[t][kb] = ((kb * 16 + g8) << 8) + slot * 8;
    }

    // ---- fragment load offsets
    const int aslot = ((lane ^ ((lane >> 3) & 3)) << 4);

    float acc[4][4][4];
#pragma unroll
    for (int mi = 0; mi < 4; mi++)
#pragma unroll
        for (int ni = 0; ni < 4; ni++)
#pragma unroll
            for (int r = 0; r < 4; r++) acc[mi][ni][r] = 0.f;

    const int NC = K / BK;

    // prologue: chunk 0 -> buffer 0
    {
        const float4 av0 = *reinterpret_cast<const float4*>(A + (size_t)(row0 + ar) * K + ac);
        const float4 av1 = *reinterpret_cast<const float4*>(A + (size_t)(row0 + 64 + ar) * K + ac);
        const float a0[4] = {av0.x, av0.y, av0.z, av0.w};
        const float a1[4] = {av1.x, av1.y, av1.z, av1.w};
#pragma unroll
        for (int j = 0; j < 4; j++) {
            *reinterpret_cast<uint32_t*>(Asm + aoff[j]) = f2tf32(a0[j]);
            *reinterpret_cast<uint32_t*>(Asm + aoff[j] + 2048) = f2tf32(a1[j]);
        }
        float wreg[2][4];
#pragma unroll
        for (int t = 0; t < 2; t++)
#pragma unroll
            for (int s = 0; s < 4; s++)
                wreg[t][s] = W[(size_t)(kq + s * 4) * N + col0 + nn + t * 64];
#pragma unroll
        for (int t = 0; t < 2; t++)
#pragma unroll
            for (int kb = 0; kb < 2; kb++) {
                uint2 u = {f2tf32(wreg[t][kb * 2 + 0]), f2tf32(wreg[t][kb * 2 + 1])};
                *reinterpret_cast<uint2*>(Bsm + boff[t][kb]) = u;
            }
    }
    __syncthreads();

    for (int c = 0; c < NC; c++) {
        const int buf = c & 1;
        const char* Ab = Asm + buf * 8192;
        const char* Bb = Bsm + buf * 8192;

        float4 av0, av1;
        float wreg[2][4];
        if (c + 1 < NC) {
            const int k0 = (c + 1) * BK;
            av0 = *reinterpret_cast<const float4*>(A + (size_t)(row0 + ar) * K + k0 + ac);
            av1 = *reinterpret_cast<const float4*>(A + (size_t)(row0 + 64 + ar) * K + k0 + ac);
#pragma unroll
            for (int t = 0; t < 2; t++)
#pragma unroll
                for (int s = 0; s < 4; s++)
                    wreg[t][s] = W[(size_t)(k0 + kq + s * 4) * N + col0 + nn + t * 64];
        }

#pragma unroll
        for (int kb = 0; kb < 2; kb++) {
            const char* Abk = Ab + (kb << 12);
            const char* Bbk = Bb + (kb << 12);
            uint4 afr[4];
            uint2 bfr[4];
#pragma unroll
            for (int mi = 0; mi < 4; mi++)
                afr[mi] = *reinterpret_cast<const uint4*>(Abk + ((g16b + mi) << 9) + aslot);
#pragma unroll
            for (int ni = 0; ni < 4; ni++) {
                const int g8 = bg8 + ni;
                bfr[ni] = *reinterpret_cast<const uint2*>(Bbk + (g8 << 8) + ((lane ^ (g8 & 3)) << 3));
            }
#pragma unroll
            for (int mi = 0; mi < 4; mi++)
#pragma unroll
                for (int ni = 0; ni < 4; ni++)
                    mma_tf32(acc[mi][ni],
                             reinterpret_cast<const uint32_t*>(&afr[mi]),
                             reinterpret_cast<const uint32_t*>(&bfr[ni]));
        }

        if (c + 1 < NC) {
            __syncthreads();
            char* An = Asm + (buf ^ 1) * 8192;
            char* Bn = Bsm + (buf ^ 1) * 8192;
            const float a0[4] = {av0.x, av0.y, av0.z, av0.w};
            const float a1[4] = {av1.x, av1.y, av1.z, av1.w};
#pragma unroll
            for (int j = 0; j < 4; j++) {
                *reinterpret_cast<uint32_t*>(An + aoff[j]) = f2tf32(a0[j]);
                *reinterpret_cast<uint32_t*>(An + aoff[j] + 2048) = f2tf32(a1[j]);
            }
#pragma unroll
            for (int t = 0; t < 2; t++)
#pragma unroll
                for (int kb = 0; kb < 2; kb++) {
                    uint2 u = {f2tf32(wreg[t][kb * 2 + 0]), f2tf32(wreg[t][kb * 2 + 1])};
                    *reinterpret_cast<uint2*>(Bn + boff[t][kb]) = u;
                }
            __syncthreads();
        }
    }

    // epilogue
    const int lg = lane >> 2, lt = lane & 3;
#pragma unroll
    for (int mi = 0; mi < 4; mi++) {
#pragma unroll
        for (int half = 0; half < 2; half++) {
            const int r = row0 + m0w + mi * 16 + lg + half * 8;
#pragma unroll
            for (int ni = 0; ni < 4; ni++) {
                const int cc = col0 + n0w + ni * 8 + lt * 2;
                float2 o;
                o.x = acc[mi][ni][half * 2 + 0] + bias[cc];
                o.y = acc[mi][ni][half * 2 + 1] + bias[cc + 1];
                if (act == 1) {
                    o.x = 0.5f * o.x * (1.0f + erff(o.x * 0.70710678118654752f));
                    o.y = 0.5f * o.y * (1.0f + erff(o.y * 0.70710678118654752f));
                }
                if (res) {
                    const float2 rv = *reinterpret_cast<const float2*>(res + (size_t)r * N + cc);
                    o.x += rv.x; o.y += rv.y;
                }
                *reinterpret_cast<float2*>(C + (size_t)r * N + cc) = o;
            }
        }
    }
}

// ---------------- LayerNorm ----------------
__global__ __launch_bounds__(256) void ln_kernel(const float* __restrict__ x,
                                                 const float* __restrict__ g,
                                                 const float* __restrict__ b,
                                                 float* __restrict__ out)
{
    const int row = blockIdx.x;
    const float* xr = x + (size_t)row * D_;
    float* outr = out + (size_t)row * D_;
    const int tid = threadIdx.x;

    float4 v = reinterpret_cast<const float4*>(xr)[tid];
    float s = v.x + v.y + v.z + v.w;
    float ss = v.x * v.x + v.y * v.y + v.z * v.z + v.w * v.w;

    __shared__ float sh_s[8], sh_ss[8];
    for (int off = 16; off; off >>= 1) {
        s  += __shfl_xor_sync(0xffffffffu, s, off);
        ss += __shfl_xor_sync(0xffffffffu, ss, off);
    }
    const int wid = tid >> 5, lane = tid & 31;
    if (lane == 0) { sh_s[wid] = s; sh_ss[wid] = ss; }
    __syncthreads();
    if (wid == 0) {
        s  = (lane < 8) ? sh_s[lane]  : 0.f;
        ss = (lane < 8) ? sh_ss[lane] : 0.f;
        for (int off = 4; off; off >>= 1) {
            s  += __shfl_xor_sync(0xffffffffu, s, off);
            ss += __shfl_xor_sync(0xffffffffu, ss, off);
        }
        if (lane == 0) { sh_s[0] = s; sh_ss[0] = ss; }
    }
    __syncthreads();
    const float mu = sh_s[0] * (1.0f / D_);
    const float var = sh_ss[0] * (1.0f / D_) - mu * mu;
    const float rstd = rsqrtf(var + 1e-5f);

    float4 gv = reinterpret_cast<const float4*>(g)[tid];
    float4 bv = reinterpret_cast<const float4*>(b)[tid];
    float4 o;
    o.x = (v.x - mu) * rstd * gv.x + bv.x;
    o.y = (v.y - mu) * rstd * gv.y + bv.y;
    o.z = (v.z - mu) * rstd * gv.z + bv.z;
    o.w = (v.w - mu) * rstd * gv.w + bv.w;
    reinterpret_cast<float4*>(outr)[tid] = o;
}

// ================= sparse attention v2: smem K/V tile, lane-parallel keys =====
// CTA = (64-query block, head, batch). 256 threads = 8 warps x 8 queries each.
// Smem holds key window rows [qb0-128, qb0+63] (192 rows, pad 65 floats).
#define QB 64
#define KW 192
#define KP 65
#define ATTN_SMEM (2 * KW * KP * 4)

__global__ __launch_bounds__(256) void attn2_kernel(const float* __restrict__ Q,
                                                    const float* __restrict__ K,
                                                    const float* __restrict__ V,
                                                    const int* __restrict__ mask,
                                                    float* __restrict__ O)
{
    extern __shared__ float smattn[];
    float* Ks = smattn;
    float* Vs = smattn + KW * KP;

    const int qb0 = blockIdx.x * QB;
    const int h = blockIdx.y;
    const int b = blockIdx.z;
    const int tid = threadIdx.x;
    const int warp = tid >> 5, lane = tid & 31;
    const int base_row = qb0 - 128;

    // stage K/V window
    for (int idx = tid; idx < KW * 64; idx += 256) {
        const int r = idx >> 6, d = idx & 63;
        const int j = base_row + r;
        if (j >= 0) {
            const size_t g = ((size_t)(b * S_ + j)) * D_ + h * 64 + d;
            Ks[r * KP + d] = K[g];
            Vs[r * KP + d] = V[g];
        }
    }
    __syncthreads();

#pragma unroll 1
    for (int qi = 0; qi < 8; qi++) {
        const int i = qb0 + warp * 8 + qi;
        const float* qrow = Q + ((size_t)(b * S_ + i)) * D_ + h * 64;
        float rq[64];
#pragma unroll
        for (int d = 0; d < 64; d++) rq[d] = __ldg(qrow + d);
        const int* mrow = mask + (size_t)i * S_;

        float m = -INFINITY, l = 0.f, acc0 = 0.f, acc1 = 0.f;

        // ---- strided keys: lane l handles j = i - 256 - 128*l ----
        {
            const int j = i - 256 - 128 * lane;
            float s = -INFINITY;
            if (j >= 0) {
                const float* kr = K + ((size_t)(b * S_ + j)) * D_ + h * 64;
                float dv = 0.f;
#pragma unroll
                for (int d = 0; d < 64; d++) dv = fmaf(rq[d], __ldg(kr + d), dv);
                s = dv * 0.125f;
                if (mrow[j] == 0) s = NEG_;
            }
            float bm = s;
            for (int off = 16; off; off >>= 1)
                bm = fmaxf(bm, __shfl_xor_sync(0xffffffffu, bm, off));
            if (bm > -1e37f) {
                const float nm = fmaxf(m, bm);
                const float sc = __expf(m - nm);
                const float p = __expf(s - nm);
                float bs = p;
                for (int off = 16; off; off >>= 1)
                    bs += __shfl_xor_sync(0xffffffffu, bs, off);
                l = l * sc + bs;
                acc0 *= sc; acc1 *= sc;
                m = nm;
                const int cnt = (i - 256) / 128 + 1;  // valid lanes (i>=256 here)
                for (int l2 = 0; l2 < cnt; l2++) {
                    const float pv = __shfl_sync(0xffffffffu, p, l2);
                    const int j2 = i - 256 - 128 * l2;
                    const float* vr = V + ((size_t)(b * S_ + j2)) * D_ + h * 64;
                    acc0 = fmaf(pv, __ldg(vr + lane), acc0);
                    acc1 = fmaf(pv, __ldg(vr + lane + 32), acc1);
                }
            }
        }

        // ---- local window [i-128, i]: 5 batches of 32 ----
#pragma unroll 1
        for (int t = 0; t < 5; t++) {
            const int jb = i - 128 + t * 32;
            const int j = jb + lane;
            float s = -INFINITY;
            if (j >= 0 && j <= i) {
                const float* kr = Ks + (j - base_row) * KP;
                float dv = 0.f;
#pragma unroll
                for (int d = 0; d < 64; d++) dv = fmaf(rq[d], kr[d], dv);
                s = dv * 0.125f;
                if (mrow[j] == 0) s = NEG_;
            }
            float bm = s;
            for (int off = 16; off; off >>= 1)
                bm = fmaxf(bm, __shfl_xor_sync(0xffffffffu, bm, off));
            if (bm > -1e37f) {
                const float nm = fmaxf(m, bm);
                const float sc = __expf(m - nm);
                const float p = __expf(s - nm);
                float bs = p;
                for (int off = 16; off; off >>= 1)
                    bs += __shfl_xor_sync(0xffffffffu, bs, off);
                l = l * sc + bs;
                acc0 *= sc; acc1 *= sc;
                m = nm;
                const int l2lo = (jb < 0) ? -jb : 0;
                const int l2hi = (i - jb < 31) ? (i - jb) : 31;
                for (int l2 = l2lo; l2 <= l2hi; l2++) {
                    const float pv = __shfl_sync(0xffffffffu, p, l2);
                    const float* vr = Vs + (jb + l2 - base_row) * KP;
                    acc0 = fmaf(pv, vr[lane], acc0);
                    acc1 = fmaf(pv, vr[lane + 32], acc1);
                }
            }
        }

        const float inv = 1.0f / l;
        float* orow = O + ((size_t)(b * S_ + i)) * D_ + h * 64;
        orow[lane] = acc0 * inv;
        orow[lane + 32] = acc1 * inv;
    }
}

// ---------------- host launcher ----------------
extern "C" void kernel_launch(void* const* d_in, const int* in_sizes, int n_in,
                              void* d_out, int out_size)
{
    (void)in_sizes; (void)n_in; (void)out_size;
    const float* x    = (const float*)d_in[0];
    const int*   mask = (const int*)  d_in[1];
    const float* Wq = (const float*)d_in[2];  const float* bq = (const float*)d_in[3];
    const float* Wk = (const float*)d_in[4];  const float* bk = (const float*)d_in[5];
    const float* Wv = (const float*)d_in[6];  const float* bv = (const float*)d_in[7];
    const float* Wo = (const float*)d_in[8];  const float* bo = (const float*)d_in[9];
    const float* W1 = (const float*)d_in[10]; const float* bf1 = (const float*)d_in[11];
    const float* W2 = (const float*)d_in[12]; const float* bf2 = (const float*)d_in[13];
    const float* g1 = (const float*)d_in[14]; const float* bl1 = (const float*)d_in[15];
    const float* g2 = (const float*)d_in[16]; const float* bl2 = (const float*)d_in[17];
    float* out = (float*)d_out;

    float *n1, *q, *k, *v, *o, *x1, *n2, *ff;
    cudaGetSymbolAddress((void**)&n1, g_n1);
    cudaGetSymbolAddress((void**)&q,  g_q);
    cudaGetSymbolAddress((void**)&k,  g_k);
    cudaGetSymbolAddress((void**)&v,  g_v);
    cudaGetSymbolAddress((void**)&o,  g_o);
    cudaGetSymbolAddress((void**)&x1, g_x1);
    cudaGetSymbolAddress((void**)&n2, g_n2);
    cudaGetSymbolAddress((void**)&ff, g_ff);

    cudaFuncSetAttribute(attn2_kernel, cudaFuncAttributeMaxDynamicSharedMemorySize, ATTN_SMEM);

    const int M = B_ * S_;  // 4096

    // 1) LN1
    ln_kernel<<<M, 256>>>(x, g1, bl1, n1);

    // 2) Q, K, V projections
    {
        dim3 grid(D_ / BN, M / BM);
        mmagemm_kernel<<<grid, 256>>>(n1, Wq, bq, nullptr, q, M, D_, D_, 0);
        mmagemm_kernel<<<grid, 256>>>(n1, Wk, bk, nullptr, k, M, D_, D_, 0);
        mmagemm_kernel<<<grid, 256>>>(n1, Wv, bv, nullptr, v, M, D_, D_, 0);
    }

    // 3) sparse attention
    {
        dim3 grid(S_ / QB, H_, B_);
        attn2_kernel<<<grid, 256, ATTN_SMEM>>>(q, k, v, mask, o);
    }

    // 4) output projection + residual
    {
        dim3 grid(D_ / BN, M / BM);
        mmagemm_kernel<<<grid, 256>>>(o, Wo, bo, x, x1, M, D_, D_, 0);
    }

    // 5) LN2
    ln_kernel<<<M, 256>>>(x1, g2, bl2, n2);

    // 6) FFN up + GELU
    {
        dim3 grid(FF_ / BN, M / BM);
        mmagemm_kernel<<<grid, 256>>>(n2, W1, bf1, nullptr, ff, M, FF_, D_, 1);
    }

    // 7) FFN down + residual
    {
        dim3 grid(D_ / BN, M / BM);
        mmagemm_kernel<<<grid, 256>>>(ff, W2, bf2, x1, out, M, D_, FF_, 0);
    }
}